// round 12
// baseline (speedup 1.0000x reference)
#include <cuda_runtime.h>
#include <cuda_fp16.h>
#include <math_constants.h>

// warpLayer, round 12: 4 px/thread (128/warp) + fused int quantization +
// deg-9 atan poly; PDL overlap of build_tab with the table-free prologue.

#define NPIX  (16 * 512 * 512)
#define NCELL (255 * 255)

__device__ uint4 g_tab[NCELL * 4];   // 4.16 MB

__global__ __launch_bounds__(256)
void build_tab(const float* __restrict__ wt)
{
    int idx = blockIdx.x * blockDim.x + threadIdx.x;
    if (idx < NCELL * 4) {
        int cell = idx >> 2, k = idx & 3;
        int cp = (k == 1) ? 2 : (k == 2) ? 1 : k;   // perm {0,2,1,3}
        int i = cell / 255;
        int j = cell - i * 255;
        const float* base = wt + ((i << 8) + j) * 8 + (cp << 1);
        float2 c00 = *(const float2*)(base);
        float2 c01 = *(const float2*)(base + 8);
        float2 c10 = *(const float2*)(base + 256 * 8);
        float2 c11 = *(const float2*)(base + 256 * 8 + 8);
        const float S = 0.0005f;
        __half2 h00 = __floats2half2_rn(S * c00.x, S * c00.y);
        __half2 h01 = __floats2half2_rn(S * c01.x, S * c01.y);
        __half2 h10 = __floats2half2_rn(S * c10.x, S * c10.y);
        __half2 h11 = __floats2half2_rn(S * c11.x, S * c11.y);
        uint4 o;
        o.x = *reinterpret_cast<unsigned*>(&h00);
        o.y = *reinterpret_cast<unsigned*>(&h01);
        o.z = *reinterpret_cast<unsigned*>(&h10);
        o.w = *reinterpret_cast<unsigned*>(&h11);
        g_tab[idx] = o;
    }
    cudaTriggerProgrammaticLaunchCompletion();
}

// C = wrap(atan2(y, x)) * 255/(2*pi) in [0, 255]
__device__ __forceinline__ float angle_c(float y, float x)
{
    const float K = 255.0f / (2.0f * CUDART_PI_F);
    float ax = fabsf(x), ay = fabsf(y);
    float mx = fmaxf(ax, ay), mn = fminf(ax, ay);
    float a  = __fdividef(mn, mx);
    float s  = a * a;
    float p  =             0.0208351f;      // A&S 4.4.49, |err| <= 1e-5 rad
    p = fmaf(p, s, -0.0851330f);
    p = fmaf(p, s,  0.1801410f);
    p = fmaf(p, s, -0.3302995f);
    p = fmaf(p, s,  0.9998660f);
    float r = a * p * K;
    if (ay > ax)  r = 63.75f - r;
    if (x < 0.0f) r = 127.5f - r;
    if (y < 0.0f) r = 255.0f - r;
    return r;
}

// owner: pack (cell:16 | w0q:8 | w1q:8) via fused fixed-point quantization
__device__ __forceinline__ unsigned prep(const float4& im)
{
    float c0 = fminf(fmaxf(angle_c(im.y, im.x), 0.0f), 254.0f);
    float c1 = fminf(fmaxf(angle_c(im.w, im.z), 0.0f), 254.0f);
    int q0 = __float2int_rd(c0 * 256.0f);   // i0 = q0>>8, w0q = q0&255
    int q1 = __float2int_rd(c1 * 256.0f);
    int cell = (q0 >> 8) * 255 + (q1 >> 8);
    return ((unsigned)cell << 16) | ((unsigned)(q0 & 255) << 8)
                                  |  (unsigned)(q1 & 255);
}

// receiver: unpack w half2, bilinear on one 64B cell chunk, return packed half2
__device__ __forceinline__ unsigned bilin(const uint4& v, unsigned u)
{
    unsigned hb = __byte_perm(u, 0x64646464u, 0x4041);
    __half2 h = __hfma2(*reinterpret_cast<__half2*>(&hb),
                        __float2half2_rn(0.00390625f),      // 1/256
                        __float2half2_rn(-4.0f));           // (w0, w1)
    __half2 om = __hsub2(__float2half2_rn(1.0f), h);
    __half2 p  = __halves2half2(__high2half(om), __high2half(h));
    __half2 A0 = __hmul2(__low2half2(om), p);   // (a00, a01)
    __half2 A1 = __hmul2(__low2half2(h),  p);   // (a10, a11)

    __half2 acc = __hmul2(__low2half2(A0),  *reinterpret_cast<const __half2*>(&v.x));
    acc = __hfma2(__high2half2(A0), *reinterpret_cast<const __half2*>(&v.y), acc);
    acc = __hfma2(__low2half2(A1),  *reinterpret_cast<const __half2*>(&v.z), acc);
    acc = __hfma2(__high2half2(A1), *reinterpret_cast<const __half2*>(&v.w), acc);
    return *reinterpret_cast<unsigned*>(&acc);
}

__global__ __launch_bounds__(256, 4)
void warp_main(const float4* __restrict__ img, float4* __restrict__ out)
{
    const unsigned FULL = 0xffffffffu;
    int lane  = threadIdx.x & 31;
    int warp  = (blockIdx.x * blockDim.x + threadIdx.x) >> 5;
    int pbase = warp << 7;                 // 128 pixels per warp

    // ---- table-independent prologue (overlaps build_tab via PDL) ----
    float4 im0 = img[pbase + lane];
    float4 im1 = img[pbase + 32 + lane];
    float4 im2 = img[pbase + 64 + lane];
    float4 im3 = img[pbase + 96 + lane];

    unsigned u0 = prep(im0);
    unsigned u1 = prep(im1);
    unsigned u2 = prep(im2);
    unsigned u3 = prep(im3);

    cudaGridDependencySynchronize();

    int k = lane & 3;
    int g = lane >> 2;

    #pragma unroll
    for (int r = 0; r < 4; r++) {
        int q = r * 8 + g;

        unsigned b0 = __shfl_sync(FULL, u0, q);
        unsigned b1 = __shfl_sync(FULL, u1, q);
        unsigned b2 = __shfl_sync(FULL, u2, q);
        unsigned b3 = __shfl_sync(FULL, u3, q);

        uint4 v0 = __ldg(&g_tab[((b0 >> 16) << 2) + k]);
        uint4 v1 = __ldg(&g_tab[((b1 >> 16) << 2) + k]);
        uint4 v2 = __ldg(&g_tab[((b2 >> 16) << 2) + k]);
        uint4 v3 = __ldg(&g_tab[((b3 >> 16) << 2) + k]);

        int P0 = pbase + q;
        int P1 = pbase + 32 + q;
        int P2 = pbase + 64 + q;
        int P3 = pbase + 96 + q;
        float4 re0, re1, re2, re3;
        if (k == 2) {
            re0 = __ldg(&img[P0]); re1 = __ldg(&img[P1]);
            re2 = __ldg(&img[P2]); re3 = __ldg(&img[P3]);
        }

        unsigned a0 = bilin(v0, b0);
        unsigned a1 = bilin(v1, b1);
        unsigned a2 = bilin(v2, b2);
        unsigned a3 = bilin(v3, b3);

        unsigned x0 = __shfl_xor_sync(FULL, a0, 2);
        unsigned x1 = __shfl_xor_sync(FULL, a1, 2);
        unsigned x2 = __shfl_xor_sync(FULL, a2, 2);
        unsigned x3 = __shfl_xor_sync(FULL, a3, 2);

        if (k < 3) {
            float2 o0 = __half22float2(*reinterpret_cast<__half2*>(&a0));
            float2 e0 = __half22float2(*reinterpret_cast<__half2*>(&x0));
            float2 o1 = __half22float2(*reinterpret_cast<__half2*>(&a1));
            float2 e1 = __half22float2(*reinterpret_cast<__half2*>(&x1));
            float2 o2 = __half22float2(*reinterpret_cast<__half2*>(&a2));
            float2 e2 = __half22float2(*reinterpret_cast<__half2*>(&x2));
            float2 o3 = __half22float2(*reinterpret_cast<__half2*>(&a3));
            float2 e3 = __half22float2(*reinterpret_cast<__half2*>(&x3));
            out[(size_t)P0 * 3 + k] = (k == 2) ? re0 : make_float4(o0.x, o0.y, e0.x, e0.y);
            out[(size_t)P1 * 3 + k] = (k == 2) ? re1 : make_float4(o1.x, o1.y, e1.x, e1.y);
            out[(size_t)P2 * 3 + k] = (k == 2) ? re2 : make_float4(o2.x, o2.y, e2.x, e2.y);
            out[(size_t)P3 * 3 + k] = (k == 2) ? re3 : make_float4(o3.x, o3.y, e3.x, e3.y);
        }
    }
}

extern "C" void kernel_launch(void* const* d_in, const int* in_sizes, int n_in,
                              void* d_out, int out_size)
{
    const float4* img = (const float4*)d_in[0];
    const float*  wt  = (const float*)d_in[1];
    float4*       out = (float4*)d_out;

    build_tab<<<(NCELL * 4 + 255) / 256, 256>>>(wt);

    cudaLaunchConfig_t cfg = {};
    cfg.gridDim  = dim3(NPIX / 1024, 1, 1);
    cfg.blockDim = dim3(256, 1, 1);
    cfg.dynamicSmemBytes = 0;
    cfg.stream = 0;
    cudaLaunchAttribute attr[1];
    attr[0].id = cudaLaunchAttributeProgrammaticStreamSerialization;
    attr[0].val.programmaticStreamSerializationAllowed = 1;
    cfg.attrs = attr;
    cfg.numAttrs = 1;
    cudaLaunchKernelEx(&cfg, warp_main, img, out);
}